// round 10
// baseline (speedup 1.0000x reference)
#include <cuda_runtime.h>
#include <cuda_bf16.h>
#include <cstdint>

// ---------------------------------------------------------------------------
// YOLO loss (nc=1).  B=64, N=32, A=3, grids {160,80,40}, pred [B,18,G,G].
//
// loss = 0.05 * sum_s box_sq[s]/n_pos[s]
//      +        sum_s ( pos_plus[s]/n_pos[s] + (S_all[s]-pos_neg[s])/n_neg[s] )
//
// Dense softplus sum is MUFU-bound -> batch the logarithm:
//   sum ln(1+e^{-|x|}) over 8 elems = ln2 * log2( prod (1+2^{-|x|*log2e}) )
//   => 8 EX2 + 1 LG2 per 8 elements (1.125 MUFU/elem instead of 2)
//   sum max(x,0) = 0.5*(sum x + sum |x|)   (abs is a free operand modifier)
//
// Single kernel, 648 blocks (R8 skeleton, validated):
//   blocks [0,24):      192 warp-tasks (scale,batch) target matching
//   blocks [24,408):    s0, half obj-plane each (3200 f4)
//   blocks [408,600):   s1, one obj-plane each (1600 f4)
//   blocks [600,648):   s2, four obj-planes each (4 x 400 f4)
//   last block (ticket) reduces partials and writes the loss.
// ---------------------------------------------------------------------------

#define NN 32
#define TGT_BLOCKS 24
#define NB0D 384
#define NB1D 192
#define NB2D 48
#define DENSE_BLOCKS (NB0D + NB1D + NB2D)          // 624
#define TOTAL_BLOCKS (TGT_BLOCKS + DENSE_BLOCKS)   // 648

__device__ double   g_part[DENSE_BLOCKS];  // dense per-block partials
__device__ float4   g_tpart[192];          // target partials: sq, sp-, sp+, cnt
__device__ unsigned g_ticket;

__device__ __forceinline__ float ex2f(float x) {
    float r; asm("ex2.approx.f32 %0, %1;" : "=f"(r) : "f"(x)); return r;
}
__device__ __forceinline__ float lg2f(float x) {
    float r; asm("lg2.approx.f32 %0, %1;" : "=f"(r) : "f"(x)); return r;
}

__device__ __forceinline__ float sp(float x) {   // exact-ish softplus (target pass only)
    return fmaxf(x, 0.0f) + __logf(1.0f + __expf(-fabsf(x)));
}

struct Acc { float ax0, ax1, au0, au1, alg0, alg1; };

#define NL2E (-1.4426950408889634f)

// 8 elements -> 8 EX2 + 1 LG2
__device__ __forceinline__ void accum8(float4 a, float4 b, Acc& c) {
    float u0 = fabsf(a.x), u1 = fabsf(a.y), u2 = fabsf(a.z), u3 = fabsf(a.w);
    float u4 = fabsf(b.x), u5 = fabsf(b.y), u6 = fabsf(b.z), u7 = fabsf(b.w);
    float e0 = ex2f(u0 * NL2E), e1 = ex2f(u1 * NL2E);
    float e2 = ex2f(u2 * NL2E), e3 = ex2f(u3 * NL2E);
    float e4 = ex2f(u4 * NL2E), e5 = ex2f(u5 * NL2E);
    float e6 = ex2f(u6 * NL2E), e7 = ex2f(u7 * NL2E);
    float p0 = 1.0f + e0;
    p0 = fmaf(p0, e1, p0);
    p0 = fmaf(p0, e2, p0);
    p0 = fmaf(p0, e3, p0);
    float p1 = 1.0f + e4;
    p1 = fmaf(p1, e5, p1);
    p1 = fmaf(p1, e6, p1);
    p1 = fmaf(p1, e7, p1);
    c.alg0 += lg2f(p0 * p1);
    c.ax0 += (a.x + a.y) + (a.z + a.w);
    c.ax1 += (b.x + b.y) + (b.z + b.w);
    c.au0 += (u0 + u1) + (u2 + u3);
    c.au1 += (u4 + u5) + (u6 + u7);
}

// 4 elements -> 4 EX2 + 1 LG2
__device__ __forceinline__ void accum4(float4 a, Acc& c) {
    float u0 = fabsf(a.x), u1 = fabsf(a.y), u2 = fabsf(a.z), u3 = fabsf(a.w);
    float e0 = ex2f(u0 * NL2E), e1 = ex2f(u1 * NL2E);
    float e2 = ex2f(u2 * NL2E), e3 = ex2f(u3 * NL2E);
    float p0 = 1.0f + e0;
    p0 = fmaf(p0, e1, p0);
    p0 = fmaf(p0, e2, p0);
    p0 = fmaf(p0, e3, p0);
    c.alg1 += lg2f(p0);
    c.ax0 += (a.x + a.y) + (a.z + a.w);
    c.au0 += (u0 + u1) + (u2 + u3);
}

// NF4 float4 elements starting at p (contiguous), 256 threads.
template <int NF4>
__device__ __forceinline__ void stream_sum(const float4* __restrict__ p,
                                           int tid, Acc& a) {
    constexpr int PAIRS = NF4 / 512;
    constexpr int REM4  = NF4 - PAIRS * 512;
    constexpr int REMF  = REM4 / 256;              // 0 or 1
    constexpr int TAIL  = REM4 - REMF * 256;
    #pragma unroll
    for (int k = 0; k < PAIRS; k++) {
        float4 va = __ldg(p + (2 * k) * 256 + tid);
        float4 vb = __ldg(p + (2 * k + 1) * 256 + tid);
        accum8(va, vb, a);
    }
    if (REMF == 1)
        accum4(__ldg(p + PAIRS * 512 + tid), a);
    if (TAIL > 0 && tid < TAIL)
        accum4(__ldg(p + PAIRS * 512 + REMF * 256 + tid), a);
}

__global__ void __launch_bounds__(256, 2) yolo_kernel(
        const float* __restrict__ pred0,
        const float* __restrict__ pred1,
        const float* __restrict__ pred2,
        const float* __restrict__ boxes,
        const float* __restrict__ anchors,
        float* __restrict__ out) {
    const int bid  = blockIdx.x;
    const int tid  = threadIdx.x;
    const int lane = tid & 31;
    const int wid  = tid >> 5;

    __shared__ float  warpsum[8];
    __shared__ int    keys[8][NN];
    __shared__ double dsh[3][8];
    __shared__ double tsh[4][6];
    __shared__ bool   s_last;

    if (bid >= TGT_BLOCKS) {
        // ---------------- dense objectness pass (plane-contiguous) ----------------
        const int d = bid - TGT_BLOCKS;
        Acc a = {0.0f, 0.0f, 0.0f, 0.0f, 0.0f, 0.0f};
        if (d < NB0D) {
            // scale0: plane = 6400 f4 at plane*38400 + 25600; half = 3200 f4
            const float4* p = reinterpret_cast<const float4*>(pred0)
                            + (size_t)(d >> 1) * 38400 + 25600 + (size_t)(d & 1) * 3200;
            stream_sum<3200>(p, tid, a);
        } else if (d < NB0D + NB1D) {
            // scale1: one plane = 1600 f4 at plane*9600 + 6400
            const int pl = d - NB0D;
            const float4* p = reinterpret_cast<const float4*>(pred1)
                            + (size_t)pl * 9600 + 6400;
            stream_sum<1600>(p, tid, a);
        } else {
            // scale2: four planes of 400 f4 at plane*2400 + 1600
            const int p0 = (d - NB0D - NB1D) * 4;
            const float4* base = reinterpret_cast<const float4*>(pred2);
            stream_sum<400>(base + (size_t)(p0 + 0) * 2400 + 1600, tid, a);
            stream_sum<400>(base + (size_t)(p0 + 1) * 2400 + 1600, tid, a);
            stream_sum<400>(base + (size_t)(p0 + 2) * 2400 + 1600, tid, a);
            stream_sum<400>(base + (size_t)(p0 + 3) * 2400 + 1600, tid, a);
        }
        float v = 0.5f * ((a.ax0 + a.ax1) + (a.au0 + a.au1))
                + 0.69314718055994531f * (a.alg0 + a.alg1);

        #pragma unroll
        for (int o = 16; o > 0; o >>= 1)
            v += __shfl_down_sync(0xffffffffu, v, o);
        if (lane == 0) warpsum[wid] = v;
        __syncthreads();
        if (tid == 0) {
            double t = 0.0;
            #pragma unroll
            for (int w = 0; w < 8; w++) t += (double)warpsum[w];
            g_part[d] = t;
        }
    } else {
        // ---------------- sparse target pass: one (scale,batch) per warp ----------------
        const int task = bid * 8 + wid;          // 0..191
        const int s = task >> 6;
        const int b = task & 63;
        const int n = lane;

        const int G = (s == 0) ? 160 : (s == 1) ? 80 : 40;
        const float* pred = (s == 0) ? pred0 : (s == 1) ? pred1 : pred2;
        const int HW = G * G;

        float4 bx = reinterpret_cast<const float4*>(boxes)[b * NN + n];
        float gx = bx.x * (float)G;
        float gy = bx.y * (float)G;
        float gw = bx.z * (float)G;
        float gh = bx.w * (float)G;
        int gi = (int)gx;
        int gj = (int)gy;

        // anchor matching: argmax over a of prod(min(r,1/r)), first-max tiebreak
        float bestIou = -1.0f;
        float aw = 1.0f, ah = 1.0f;
        int best = 0;
        #pragma unroll
        for (int a = 0; a < 3; a++) {
            float Aw = anchors[s * 6 + a * 2 + 0];
            float Ah = anchors[s * 6 + a * 2 + 1];
            float rw = __fdiv_rn(Aw, gw);
            float rh = __fdiv_rn(Ah, gh);
            float iw = fminf(rw, __fdiv_rn(1.0f, rw));
            float ih = fminf(rh, __fdiv_rn(1.0f, rh));
            float iou = iw * ih;
            if (iou > bestIou) { bestIou = iou; best = a; aw = Aw; ah = Ah; }
        }

        // dedup: last write wins -> entry n live iff no later n' has same key
        int key = (best * G + gj) * G + gi;
        keys[wid][n] = key;
        __syncwarp();
        bool live = true;
        for (int m = n + 1; m < NN; m++)
            if (keys[wid][m] == key) { live = false; break; }

        float sq = 0.0f, spp = 0.0f, spm = 0.0f, cnt = 0.0f;
        if (live) {
            size_t base = (size_t)(b * 18 + best * 6) * HW + (size_t)gj * G + gi;
            float p0 = __ldg(pred + base);
            float p1 = __ldg(pred + base + (size_t)HW);
            float p2 = __ldg(pred + base + (size_t)2 * HW);
            float p3 = __ldg(pred + base + (size_t)3 * HW);
            float p4 = __ldg(pred + base + (size_t)4 * HW);

            float tx = gx - (float)gi;
            float ty = gy - (float)gj;
            float tw = logf(__fdiv_rn(gw, aw) + 1e-16f);
            float th = logf(__fdiv_rn(gh, ah) + 1e-16f);

            float d0 = p0 - tx, d1 = p1 - ty, d2 = p2 - tw, d3 = p3 - th;
            sq  = d0 * d0 + d1 * d1 + d2 * d2 + d3 * d3;
            spm = sp(-p4);
            spp = sp(p4);
            cnt = 1.0f;
        }

        #pragma unroll
        for (int o = 16; o > 0; o >>= 1) {
            sq  += __shfl_down_sync(0xffffffffu, sq,  o);
            spm += __shfl_down_sync(0xffffffffu, spm, o);
            spp += __shfl_down_sync(0xffffffffu, spp, o);
            cnt += __shfl_down_sync(0xffffffffu, cnt, o);
        }
        if (n == 0)
            g_tpart[task] = make_float4(sq, spm, spp, cnt);
    }

    // ---------------- last-block finalize ----------------
    __syncthreads();                 // all block stores done
    if (tid == 0) {
        __threadfence();             // publish this block's results
        unsigned t = atomicAdd(&g_ticket, 1u);
        s_last = (t == TOTAL_BLOCKS - 1);
    }
    __syncthreads();
    if (s_last) {
        __threadfence();
        // dense partials per scale
        double v0 = 0.0, v1 = 0.0, v2 = 0.0;
        v0 = ((volatile double*)g_part)[tid];
        if (tid < NB0D - 256) v0 += ((volatile double*)g_part)[256 + tid];
        if (tid < NB1D) v1 = ((volatile double*)g_part)[NB0D + tid];
        if (tid < NB2D) v2 = ((volatile double*)g_part)[NB0D + NB1D + tid];
        #pragma unroll
        for (int o = 16; o > 0; o >>= 1) {
            v0 += __shfl_down_sync(0xffffffffu, v0, o);
            v1 += __shfl_down_sync(0xffffffffu, v1, o);
            v2 += __shfl_down_sync(0xffffffffu, v2, o);
        }
        if (lane == 0) { dsh[0][wid] = v0; dsh[1][wid] = v1; dsh[2][wid] = v2; }

        // target partials: warp w sums tasks [w*32, w*32+32)
        if (wid < 6) {
            const volatile float* tp = (const volatile float*)g_tpart;
            int o4 = (wid * 32 + lane) * 4;
            double a  = (double)tp[o4 + 0];
            double b  = (double)tp[o4 + 1];
            double c  = (double)tp[o4 + 2];
            double dd = (double)tp[o4 + 3];
            #pragma unroll
            for (int o = 16; o > 0; o >>= 1) {
                a  += __shfl_down_sync(0xffffffffu, a,  o);
                b  += __shfl_down_sync(0xffffffffu, b,  o);
                c  += __shfl_down_sync(0xffffffffu, c,  o);
                dd += __shfl_down_sync(0xffffffffu, dd, o);
            }
            if (lane == 0) { tsh[0][wid] = a; tsh[1][wid] = b; tsh[2][wid] = c; tsh[3][wid] = dd; }
        }
        __syncthreads();

        if (tid == 0) {
            double sall0 = 0.0, sall1 = 0.0, sall2 = 0.0;
            #pragma unroll
            for (int w = 0; w < 8; w++) {
                sall0 += dsh[0][w]; sall1 += dsh[1][w]; sall2 += dsh[2][w];
            }
            const double cells[3] = {4915200.0, 1228800.0, 307200.0};
            double sall[3] = {sall0, sall1, sall2};
            double loss = 0.0;
            #pragma unroll
            for (int s = 0; s < 3; s++) {
                double box = tsh[0][2 * s] + tsh[0][2 * s + 1];
                double pp  = tsh[1][2 * s] + tsh[1][2 * s + 1];
                double pn  = tsh[2][2 * s] + tsh[2][2 * s + 1];
                double np  = tsh[3][2 * s] + tsh[3][2 * s + 1];
                double nn  = cells[s] - np;
                loss += 0.05 * box / np + pp / np + (sall[s] - pn) / nn;
            }
            g_ticket = 0u;           // reset for next replay
            out[0] = (float)loss;
        }
    }
}

extern "C" void kernel_launch(void* const* d_in, const int* in_sizes, int n_in,
                              void* d_out, int out_size) {
    (void)in_sizes; (void)n_in; (void)out_size;
    const float* pred0   = (const float*)d_in[0];
    const float* pred1   = (const float*)d_in[1];
    const float* pred2   = (const float*)d_in[2];
    const float* boxes   = (const float*)d_in[3];
    // d_in[4] = labels (unused, nc==1)
    const float* anchors = (const float*)d_in[5];
    float* out = (float*)d_out;

    yolo_kernel<<<TOTAL_BLOCKS, 256>>>(pred0, pred1, pred2, boxes, anchors, out);
}

// round 11
// speedup vs baseline: 1.0013x; 1.0013x over previous
#include <cuda_runtime.h>
#include <cuda_bf16.h>
#include <cstdint>

// ---------------------------------------------------------------------------
// YOLO loss (nc=1).  B=64, N=32, A=3, grids {160,80,40}, pred [B,18,G,G].
//
// loss = 0.05 * sum_s box_sq[s]/n_pos[s]
//      +        sum_s ( pos_plus[s]/n_pos[s] + (S_all[s]-pos_neg[s])/n_neg[s] )
//
// Evidence R2-R10: duration is pinned at ~25us e2e ~= 26MB / ~1TB/s regardless
// of memory mechanism -> memory subsystem cap (idle-state clocks).  This round:
// single-wave grid at occupancy 4 (32 warps/SM, <=64 regs) with a rotating
// named-register load pipeline (MLP~4, no local arrays), batched-log softplus
// (1.125 MUFU/elem).
//   blocks [0,24):     192 warp-tasks (scale,batch) target matching
//   blocks [24,408):   s0 dense, 3200 f4 each (12.5/thread)
//   blocks [408,504):  s1 dense, 3200 f4 each
//   blocks [504,528):  s2 dense, 3200 f4 each
//   last block (ticket) reduces partials and writes the loss.
// ---------------------------------------------------------------------------

#define NN 32
#define TGT_BLOCKS 24
#define NB0D 384
#define NB1D 96
#define NB2D 24
#define DENSE_BLOCKS (NB0D + NB1D + NB2D)          // 504
#define TOTAL_BLOCKS (TGT_BLOCKS + DENSE_BLOCKS)   // 528

__device__ double   g_part[DENSE_BLOCKS];  // dense per-block partials
__device__ float4   g_tpart[192];          // target partials: sq, sp-, sp+, cnt
__device__ unsigned g_ticket;

__device__ __forceinline__ float ex2f(float x) {
    float r; asm("ex2.approx.f32 %0, %1;" : "=f"(r) : "f"(x)); return r;
}
__device__ __forceinline__ float lg2f(float x) {
    float r; asm("lg2.approx.f32 %0, %1;" : "=f"(r) : "f"(x)); return r;
}

__device__ __forceinline__ float sp(float x) {   // target pass only
    return fmaxf(x, 0.0f) + __logf(1.0f + __expf(-fabsf(x)));
}

struct Acc { float ax0, ax1, au0, au1, alg0, alg1; };

#define NL2E (-1.4426950408889634f)

// 8 elements -> 8 EX2 + 1 LG2  (validated rel_err 0.0 in R10)
__device__ __forceinline__ void accum8(float4 a, float4 b, Acc& c) {
    float u0 = fabsf(a.x), u1 = fabsf(a.y), u2 = fabsf(a.z), u3 = fabsf(a.w);
    float u4 = fabsf(b.x), u5 = fabsf(b.y), u6 = fabsf(b.z), u7 = fabsf(b.w);
    float e0 = ex2f(u0 * NL2E), e1 = ex2f(u1 * NL2E);
    float e2 = ex2f(u2 * NL2E), e3 = ex2f(u3 * NL2E);
    float e4 = ex2f(u4 * NL2E), e5 = ex2f(u5 * NL2E);
    float e6 = ex2f(u6 * NL2E), e7 = ex2f(u7 * NL2E);
    float p0 = 1.0f + e0;
    p0 = fmaf(p0, e1, p0);
    p0 = fmaf(p0, e2, p0);
    p0 = fmaf(p0, e3, p0);
    float p1 = 1.0f + e4;
    p1 = fmaf(p1, e5, p1);
    p1 = fmaf(p1, e6, p1);
    p1 = fmaf(p1, e7, p1);
    c.alg0 += lg2f(p0 * p1);
    c.ax0 += (a.x + a.y) + (a.z + a.w);
    c.ax1 += (b.x + b.y) + (b.z + b.w);
    c.au0 += (u0 + u1) + (u2 + u3);
    c.au1 += (u4 + u5) + (u6 + u7);
}

// 4 elements -> 4 EX2 + 1 LG2
__device__ __forceinline__ void accum4(float4 a, Acc& c) {
    float u0 = fabsf(a.x), u1 = fabsf(a.y), u2 = fabsf(a.z), u3 = fabsf(a.w);
    float e0 = ex2f(u0 * NL2E), e1 = ex2f(u1 * NL2E);
    float e2 = ex2f(u2 * NL2E), e3 = ex2f(u3 * NL2E);
    float p0 = 1.0f + e0;
    p0 = fmaf(p0, e1, p0);
    p0 = fmaf(p0, e2, p0);
    p0 = fmaf(p0, e3, p0);
    c.alg1 += lg2f(p0);
    c.ax0 += (a.x + a.y) + (a.z + a.w);
    c.au0 += (u0 + u1) + (u2 + u3);
}

// gathered obj f4 index -> physical f4 pointer
// idx = p*HW4 + pos (p = b*3+a) ; phys = idx + 5*p*HW4 + 4*HW4
template <int HW4>
__device__ __forceinline__ const float4* objp(const float4* __restrict__ p4, int idx) {
    int p = idx / HW4;                       // compile-time magic-mul
    return p4 + (size_t)(idx + (5 * HW4) * p + 4 * HW4);
}

// 3200 gathered f4 per block: 6 pairs (12 f4) per thread + half-block tail.
// Rotating named-register pipeline: pair k+1 loads while pair k computes.
template <int HW4>
__device__ __forceinline__ void dense3200(const float4* __restrict__ p4,
                                          int gbase, int tid, Acc& c) {
    int g = gbase + tid;
    float4 a0 = __ldg(objp<HW4>(p4, g));
    float4 b0 = __ldg(objp<HW4>(p4, g + 256));
    #pragma unroll
    for (int k = 0; k < 5; k++) {
        float4 a1 = __ldg(objp<HW4>(p4, g + (2 * k + 2) * 256));
        float4 b1 = __ldg(objp<HW4>(p4, g + (2 * k + 3) * 256));
        accum8(a0, b0, c);
        a0 = a1; b0 = b1;
    }
    accum8(a0, b0, c);
    if (tid < 128)
        accum4(__ldg(objp<HW4>(p4, gbase + 3072 + tid)), c);
}

__global__ void __launch_bounds__(256, 4) yolo_kernel(
        const float* __restrict__ pred0,
        const float* __restrict__ pred1,
        const float* __restrict__ pred2,
        const float* __restrict__ boxes,
        const float* __restrict__ anchors,
        float* __restrict__ out) {
    const int bid  = blockIdx.x;
    const int tid  = threadIdx.x;
    const int lane = tid & 31;
    const int wid  = tid >> 5;

    __shared__ float  warpsum[8];
    __shared__ int    keys[8][NN];
    __shared__ double dsh[3][8];
    __shared__ double tsh[4][6];
    __shared__ bool   s_last;

    if (bid >= TGT_BLOCKS) {
        // ---------------- dense objectness pass ----------------
        const int d = bid - TGT_BLOCKS;
        Acc a = {0.0f, 0.0f, 0.0f, 0.0f, 0.0f, 0.0f};
        if (d < NB0D) {
            dense3200<6400>(reinterpret_cast<const float4*>(pred0), d * 3200, tid, a);
        } else if (d < NB0D + NB1D) {
            dense3200<1600>(reinterpret_cast<const float4*>(pred1),
                            (d - NB0D) * 3200, tid, a);
        } else {
            dense3200< 400>(reinterpret_cast<const float4*>(pred2),
                            (d - NB0D - NB1D) * 3200, tid, a);
        }
        float v = 0.5f * ((a.ax0 + a.ax1) + (a.au0 + a.au1))
                + 0.69314718055994531f * (a.alg0 + a.alg1);

        #pragma unroll
        for (int o = 16; o > 0; o >>= 1)
            v += __shfl_down_sync(0xffffffffu, v, o);
        if (lane == 0) warpsum[wid] = v;
        __syncthreads();
        if (tid == 0) {
            double t = 0.0;
            #pragma unroll
            for (int w = 0; w < 8; w++) t += (double)warpsum[w];
            g_part[d] = t;
        }
    } else {
        // ---------------- sparse target pass: one (scale,batch) per warp ----------------
        const int task = bid * 8 + wid;          // 0..191
        const int s = task >> 6;
        const int b = task & 63;
        const int n = lane;

        const int G = (s == 0) ? 160 : (s == 1) ? 80 : 40;
        const float* pred = (s == 0) ? pred0 : (s == 1) ? pred1 : pred2;
        const int HW = G * G;

        float4 bx = reinterpret_cast<const float4*>(boxes)[b * NN + n];
        float gx = bx.x * (float)G;
        float gy = bx.y * (float)G;
        float gw = bx.z * (float)G;
        float gh = bx.w * (float)G;
        int gi = (int)gx;
        int gj = (int)gy;

        // anchor matching: argmax over a of prod(min(r,1/r)), first-max tiebreak
        float bestIou = -1.0f;
        float aw = 1.0f, ah = 1.0f;
        int best = 0;
        #pragma unroll
        for (int a = 0; a < 3; a++) {
            float Aw = anchors[s * 6 + a * 2 + 0];
            float Ah = anchors[s * 6 + a * 2 + 1];
            float rw = __fdiv_rn(Aw, gw);
            float rh = __fdiv_rn(Ah, gh);
            float iw = fminf(rw, __fdiv_rn(1.0f, rw));
            float ih = fminf(rh, __fdiv_rn(1.0f, rh));
            float iou = iw * ih;
            if (iou > bestIou) { bestIou = iou; best = a; aw = Aw; ah = Ah; }
        }

        // dedup: last write wins -> entry n live iff no later n' has same key
        int key = (best * G + gj) * G + gi;
        keys[wid][n] = key;
        __syncwarp();
        bool live = true;
        for (int m = n + 1; m < NN; m++)
            if (keys[wid][m] == key) { live = false; break; }

        float sq = 0.0f, spp = 0.0f, spm = 0.0f, cnt = 0.0f;
        if (live) {
            size_t base = (size_t)(b * 18 + best * 6) * HW + (size_t)gj * G + gi;
            float p0 = __ldg(pred + base);
            float p1 = __ldg(pred + base + (size_t)HW);
            float p2 = __ldg(pred + base + (size_t)2 * HW);
            float p3 = __ldg(pred + base + (size_t)3 * HW);
            float p4 = __ldg(pred + base + (size_t)4 * HW);

            float tx = gx - (float)gi;
            float ty = gy - (float)gj;
            float tw = logf(__fdiv_rn(gw, aw) + 1e-16f);
            float th = logf(__fdiv_rn(gh, ah) + 1e-16f);

            float d0 = p0 - tx, d1 = p1 - ty, d2 = p2 - tw, d3 = p3 - th;
            sq  = d0 * d0 + d1 * d1 + d2 * d2 + d3 * d3;
            spm = sp(-p4);
            spp = sp(p4);
            cnt = 1.0f;
        }

        #pragma unroll
        for (int o = 16; o > 0; o >>= 1) {
            sq  += __shfl_down_sync(0xffffffffu, sq,  o);
            spm += __shfl_down_sync(0xffffffffu, spm, o);
            spp += __shfl_down_sync(0xffffffffu, spp, o);
            cnt += __shfl_down_sync(0xffffffffu, cnt, o);
        }
        if (n == 0)
            g_tpart[task] = make_float4(sq, spm, spp, cnt);
    }

    // ---------------- last-block finalize ----------------
    __syncthreads();
    if (tid == 0) {
        __threadfence();
        unsigned t = atomicAdd(&g_ticket, 1u);
        s_last = (t == TOTAL_BLOCKS - 1);
    }
    __syncthreads();
    if (s_last) {
        __threadfence();
        // dense partials per scale
        double v0 = 0.0, v1 = 0.0, v2 = 0.0;
        v0 = ((volatile double*)g_part)[tid];
        if (tid < NB0D - 256) v0 += ((volatile double*)g_part)[256 + tid];
        if (tid < NB1D) v1 = ((volatile double*)g_part)[NB0D + tid];
        if (tid < NB2D) v2 = ((volatile double*)g_part)[NB0D + NB1D + tid];
        #pragma unroll
        for (int o = 16; o > 0; o >>= 1) {
            v0 += __shfl_down_sync(0xffffffffu, v0, o);
            v1 += __shfl_down_sync(0xffffffffu, v1, o);
            v2 += __shfl_down_sync(0xffffffffu, v2, o);
        }
        if (lane == 0) { dsh[0][wid] = v0; dsh[1][wid] = v1; dsh[2][wid] = v2; }

        // target partials: warp w sums tasks [w*32, w*32+32)
        if (wid < 6) {
            const volatile float* tp = (const volatile float*)g_tpart;
            int o4 = (wid * 32 + lane) * 4;
            double a  = (double)tp[o4 + 0];
            double b  = (double)tp[o4 + 1];
            double c  = (double)tp[o4 + 2];
            double dd = (double)tp[o4 + 3];
            #pragma unroll
            for (int o = 16; o > 0; o >>= 1) {
                a  += __shfl_down_sync(0xffffffffu, a,  o);
                b  += __shfl_down_sync(0xffffffffu, b,  o);
                c  += __shfl_down_sync(0xffffffffu, c,  o);
                dd += __shfl_down_sync(0xffffffffu, dd, o);
            }
            if (lane == 0) { tsh[0][wid] = a; tsh[1][wid] = b; tsh[2][wid] = c; tsh[3][wid] = dd; }
        }
        __syncthreads();

        if (tid == 0) {
            double sall0 = 0.0, sall1 = 0.0, sall2 = 0.0;
            #pragma unroll
            for (int w = 0; w < 8; w++) {
                sall0 += dsh[0][w]; sall1 += dsh[1][w]; sall2 += dsh[2][w];
            }
            const double cells[3] = {4915200.0, 1228800.0, 307200.0};
            double sall[3] = {sall0, sall1, sall2};
            double loss = 0.0;
            #pragma unroll
            for (int s = 0; s < 3; s++) {
                double box = tsh[0][2 * s] + tsh[0][2 * s + 1];
                double pp  = tsh[1][2 * s] + tsh[1][2 * s + 1];
                double pn  = tsh[2][2 * s] + tsh[2][2 * s + 1];
                double np  = tsh[3][2 * s] + tsh[3][2 * s + 1];
                double nn  = cells[s] - np;
                loss += 0.05 * box / np + pp / np + (sall[s] - pn) / nn;
            }
            g_ticket = 0u;           // reset for next replay
            out[0] = (float)loss;
        }
    }
}

extern "C" void kernel_launch(void* const* d_in, const int* in_sizes, int n_in,
                              void* d_out, int out_size) {
    (void)in_sizes; (void)n_in; (void)out_size;
    const float* pred0   = (const float*)d_in[0];
    const float* pred1   = (const float*)d_in[1];
    const float* pred2   = (const float*)d_in[2];
    const float* boxes   = (const float*)d_in[3];
    // d_in[4] = labels (unused, nc==1)
    const float* anchors = (const float*)d_in[5];
    float* out = (float*)d_out;

    yolo_kernel<<<TOTAL_BLOCKS, 256>>>(pred0, pred1, pred2, boxes, anchors, out);
}